// round 1
// baseline (speedup 1.0000x reference)
#include <cuda_runtime.h>
#include <cuda_bf16.h>

#define N_NODES_MAX 50000
#define D 64

// Scratch (no cudaMalloc allowed): accumulator + hidden layer output
__device__ float g_agg[N_NODES_MAX * D];
__device__ float g_h1 [N_NODES_MAX * D];

// ---------------------------------------------------------------------------
// Zero a float4 buffer
// ---------------------------------------------------------------------------
__global__ void zero_kernel(float4* __restrict__ p, int n4) {
    int i = blockIdx.x * blockDim.x + threadIdx.x;
    int stride = gridDim.x * blockDim.x;
    float4 z = make_float4(0.f, 0.f, 0.f, 0.f);
    for (; i < n4; i += stride) p[i] = z;
}

// ---------------------------------------------------------------------------
// Edge scatter: agg[dst] += h[src]  (16 threads per edge, float4 each)
// ---------------------------------------------------------------------------
__global__ void scatter_add_kernel(const float* __restrict__ h,
                                   const int* __restrict__ src,
                                   const int* __restrict__ dst,
                                   float* __restrict__ agg,
                                   int n_edges) {
    int idx = blockIdx.x * blockDim.x + threadIdx.x;
    int e = idx >> 4;
    if (e >= n_edges) return;
    int c = (idx & 15) << 2;   // float offset within row, multiple of 4
    int s = __ldg(src + e);
    int d = __ldg(dst + e);
    float4 val = *reinterpret_cast<const float4*>(h + (size_t)s * D + c);
    float4* p = reinterpret_cast<float4*>(agg + (size_t)d * D + c);
    atomicAdd(p, val);   // sm_90+: RED.E.ADD.F32 x4 (vectorized)
}

// ---------------------------------------------------------------------------
// Y = relu(X @ W + b), X:[n,64] W:[64,64] b:[64]. Thread-per-row, W in smem.
// ---------------------------------------------------------------------------
__global__ __launch_bounds__(256) void gemm_relu_kernel(
    const float* __restrict__ X, const float* __restrict__ W,
    const float* __restrict__ b, float* __restrict__ Y, int n) {
    __shared__ float4 Ws[D * 16];   // W[k][j] row-major, float4 over j
    __shared__ float  bs[D];
    int tid = threadIdx.x;
    for (int i = tid; i < D * 16; i += 256) Ws[i] = reinterpret_cast<const float4*>(W)[i];
    if (tid < D) bs[tid] = b[tid];
    __syncthreads();

    int row = blockIdx.x * 256 + tid;
    if (row >= n) return;
    const float4* xr = reinterpret_cast<const float4*>(X + (size_t)row * D);

    float4 acc[16];
    #pragma unroll
    for (int j = 0; j < 16; j++) acc[j] = reinterpret_cast<const float4*>(bs)[j];

    #pragma unroll 4
    for (int kc = 0; kc < 16; kc++) {
        float4 x = xr[kc];
        int kb = kc * 4;
        #pragma unroll
        for (int j = 0; j < 16; j++) {
            float4 a = acc[j];
            float4 w;
            w = Ws[(kb + 0) * 16 + j];
            a.x += x.x * w.x; a.y += x.x * w.y; a.z += x.x * w.z; a.w += x.x * w.w;
            w = Ws[(kb + 1) * 16 + j];
            a.x += x.y * w.x; a.y += x.y * w.y; a.z += x.y * w.z; a.w += x.y * w.w;
            w = Ws[(kb + 2) * 16 + j];
            a.x += x.z * w.x; a.y += x.z * w.y; a.z += x.z * w.z; a.w += x.z * w.w;
            w = Ws[(kb + 3) * 16 + j];
            a.x += x.w * w.x; a.y += x.w * w.y; a.z += x.w * w.z; a.w += x.w * w.w;
            acc[j] = a;
        }
    }

    float4* yr = reinterpret_cast<float4*>(Y + (size_t)row * D);
    #pragma unroll
    for (int j = 0; j < 16; j++) {
        float4 a = acc[j];
        a.x = fmaxf(a.x, 0.f); a.y = fmaxf(a.y, 0.f);
        a.z = fmaxf(a.z, 0.f); a.w = fmaxf(a.w, 0.f);
        yr[j] = a;
    }
}

// ---------------------------------------------------------------------------
// Layer-2 GEMM + relu + both heads fused.
// h2 = relu(X @ W2 + b2); xa = h2 @ Wa + ba [n,2]; xb = h2 @ Wb + bb [n,16]
// ---------------------------------------------------------------------------
__global__ __launch_bounds__(256) void gemm_heads_kernel(
    const float* __restrict__ X, const float* __restrict__ W,
    const float* __restrict__ b,
    const float* __restrict__ Wa, const float* __restrict__ ba,
    const float* __restrict__ Wb, const float* __restrict__ bb,
    float* __restrict__ xa_out, float* __restrict__ xb_out, int n) {
    __shared__ float4 Ws[D * 16];
    __shared__ float  bs[D];
    __shared__ float  Was[D * 2];
    __shared__ float  Wbs[D * 16];
    __shared__ float  bas[2];
    __shared__ float  bbs[16];
    int tid = threadIdx.x;
    for (int i = tid; i < D * 16; i += 256) Ws[i] = reinterpret_cast<const float4*>(W)[i];
    for (int i = tid; i < D * 16; i += 256) Wbs[i] = Wb[i];
    if (tid < D * 2) Was[tid] = Wa[tid];
    if (tid < D) bs[tid] = b[tid];
    if (tid < 2) bas[tid] = ba[tid];
    if (tid < 16) bbs[tid] = bb[tid];
    __syncthreads();

    int row = blockIdx.x * 256 + tid;
    if (row >= n) return;
    const float4* xr = reinterpret_cast<const float4*>(X + (size_t)row * D);

    float4 acc[16];
    #pragma unroll
    for (int j = 0; j < 16; j++) acc[j] = reinterpret_cast<const float4*>(bs)[j];

    #pragma unroll 4
    for (int kc = 0; kc < 16; kc++) {
        float4 x = xr[kc];
        int kb = kc * 4;
        #pragma unroll
        for (int j = 0; j < 16; j++) {
            float4 a = acc[j];
            float4 w;
            w = Ws[(kb + 0) * 16 + j];
            a.x += x.x * w.x; a.y += x.x * w.y; a.z += x.x * w.z; a.w += x.x * w.w;
            w = Ws[(kb + 1) * 16 + j];
            a.x += x.y * w.x; a.y += x.y * w.y; a.z += x.y * w.z; a.w += x.y * w.w;
            w = Ws[(kb + 2) * 16 + j];
            a.x += x.z * w.x; a.y += x.z * w.y; a.z += x.z * w.z; a.w += x.z * w.w;
            w = Ws[(kb + 3) * 16 + j];
            a.x += x.w * w.x; a.y += x.w * w.y; a.z += x.w * w.z; a.w += x.w * w.w;
            acc[j] = a;
        }
    }

    // relu into h (registers)
    float h[D];
    #pragma unroll
    for (int j = 0; j < 16; j++) {
        h[4*j+0] = fmaxf(acc[j].x, 0.f);
        h[4*j+1] = fmaxf(acc[j].y, 0.f);
        h[4*j+2] = fmaxf(acc[j].z, 0.f);
        h[4*j+3] = fmaxf(acc[j].w, 0.f);
    }

    // frame head [2]
    float a0 = bas[0], a1 = bas[1];
    #pragma unroll
    for (int j = 0; j < D; j++) {
        a0 += h[j] * Was[j * 2 + 0];
        a1 += h[j] * Was[j * 2 + 1];
    }
    xa_out[(size_t)row * 2 + 0] = a0;
    xa_out[(size_t)row * 2 + 1] = a1;

    // role head [16]
    float hb[16];
    #pragma unroll
    for (int t = 0; t < 16; t++) hb[t] = bbs[t];
    #pragma unroll
    for (int j = 0; j < D; j++) {
        float hv = h[j];
        #pragma unroll
        for (int t = 0; t < 16; t++) hb[t] += hv * Wbs[j * 16 + t];
    }
    float4* out4 = reinterpret_cast<float4*>(xb_out + (size_t)row * 16);
    #pragma unroll
    for (int q = 0; q < 4; q++)
        out4[q] = make_float4(hb[4*q+0], hb[4*q+1], hb[4*q+2], hb[4*q+3]);
}

// ---------------------------------------------------------------------------
extern "C" void kernel_launch(void* const* d_in, const int* in_sizes, int n_in,
                              void* d_out, int out_size) {
    const float* v   = (const float*)d_in[0];
    const int*   src = (const int*)  d_in[1];
    const int*   dst = (const int*)  d_in[2];
    const float* W1  = (const float*)d_in[3];
    const float* b1  = (const float*)d_in[4];
    const float* W2  = (const float*)d_in[5];
    const float* b2  = (const float*)d_in[6];
    const float* Wa  = (const float*)d_in[7];
    const float* ba  = (const float*)d_in[8];
    const float* Wb  = (const float*)d_in[9];
    const float* bb  = (const float*)d_in[10];

    int n_nodes = in_sizes[0] / D;
    int n_edges = in_sizes[1];

    float* agg; cudaGetSymbolAddress((void**)&agg, g_agg);
    float* h1;  cudaGetSymbolAddress((void**)&h1,  g_h1);

    float* xa_out = (float*)d_out;                       // [n, 2]
    float* xb_out = (float*)d_out + (size_t)n_nodes * 2; // [n, 16]

    int n4 = n_nodes * D / 4;
    int zero_blocks = 1024;
    int scat_threads = n_edges * 16;
    int scat_blocks = (scat_threads + 255) / 256;
    int gemm_blocks = (n_nodes + 255) / 256;

    // Layer 1
    zero_kernel<<<zero_blocks, 256>>>((float4*)agg, n4);
    scatter_add_kernel<<<scat_blocks, 256>>>(v, src, dst, agg, n_edges);
    gemm_relu_kernel<<<gemm_blocks, 256>>>(agg, W1, b1, h1, n_nodes);

    // Layer 2 + heads
    zero_kernel<<<zero_blocks, 256>>>((float4*)agg, n4);
    scatter_add_kernel<<<scat_blocks, 256>>>(h1, src, dst, agg, n_edges);
    gemm_heads_kernel<<<gemm_blocks, 256>>>(agg, W2, b2, Wa, ba, Wb, bb,
                                            xa_out, xb_out, n_nodes);
}